// round 16
// baseline (speedup 1.0000x reference)
#include <cuda_runtime.h>
#include <math.h>

// Fixed shape: N=100000, E=1600000, all dims 64.
#define MAXN 100000
#define MAXE 1600000
#define D 64
#define SCAN_B 1024
#define NBLK 128   // >= ceil(MAXN/SCAN_B) = 98

// Scratch (device globals; no allocation allowed)
__device__ float g_h1 [MAXN * D];
__device__ float g_h2 [MAXN * D];
__device__ int   g_deg[MAXN];
__device__ int   g_off[MAXN];
__device__ int   g_cur[MAXN];
__device__ int   g_srcidx[MAXE];
__device__ float g_invdeg[MAXN];
__device__ int   g_blocksum[NBLK];
__device__ int   g_blockoff[NBLK];

// Packed f32x2 helpers (sm_100+)
__device__ __forceinline__ unsigned long long fma2(
    unsigned long long a, unsigned long long b, unsigned long long c) {
    unsigned long long d;
    asm("fma.rn.f32x2 %0, %1, %2, %3;" : "=l"(d) : "l"(a), "l"(b), "l"(c));
    return d;
}
__device__ __forceinline__ unsigned long long splat2(float x) {
    unsigned long long d;
    asm("mov.b64 %0, {%1, %1};" : "=l"(d) : "f"(x));
    return d;
}
__device__ __forceinline__ void unpack2(unsigned long long v, float& lo, float& hi) {
    asm("mov.b64 {%0, %1}, %2;" : "=f"(lo), "=f"(hi) : "l"(v));
}

// ---------------------------------------------------------------------------
// CSR build
// ---------------------------------------------------------------------------
__global__ void zero_deg_kernel(int n) {
    int i = blockIdx.x * blockDim.x + threadIdx.x;
    if (i < n) g_deg[i] = 0;
}

__global__ void deg_kernel(const int* __restrict__ dst, int E) {
    int e = blockIdx.x * blockDim.x + threadIdx.x;
    if (e < E) atomicAdd(&g_deg[dst[e]], 1);
}

// Phase A: coalesced per-block reduction of deg
__global__ __launch_bounds__(SCAN_B) void scanA_kernel(int n) {
    int i = blockIdx.x * SCAN_B + threadIdx.x;
    int v = (i < n) ? g_deg[i] : 0;
#pragma unroll
    for (int o = 16; o; o >>= 1) v += __shfl_xor_sync(0xffffffffu, v, o);
    __shared__ int ws[32];
    if ((threadIdx.x & 31) == 0) ws[threadIdx.x >> 5] = v;
    __syncthreads();
    if (threadIdx.x < 32) {
        int s = ws[threadIdx.x];
#pragma unroll
        for (int o = 16; o; o >>= 1) s += __shfl_xor_sync(0xffffffffu, s, o);
        if (threadIdx.x == 0) g_blocksum[blockIdx.x] = s;
    }
}

// Phase B: single-block exclusive scan of block sums
__global__ __launch_bounds__(NBLK) void scanB_kernel(int nb) {
    __shared__ int s[NBLK];
    int t = threadIdx.x;
    int v = (t < nb) ? g_blocksum[t] : 0;
    s[t] = v;
    __syncthreads();
    for (int o = 1; o < NBLK; o <<= 1) {
        int u = (t >= o) ? s[t - o] : 0;
        __syncthreads();
        s[t] += u;
        __syncthreads();
    }
    g_blockoff[t] = s[t] - v;   // exclusive
}

// Phase C: per-block exclusive scan + offset; emits off/cur/invdeg (coalesced)
__global__ __launch_bounds__(SCAN_B) void scanC_kernel(int n) {
    __shared__ int sm[SCAN_B];
    int i = blockIdx.x * SCAN_B + threadIdx.x;
    int t = threadIdx.x;
    int v = (i < n) ? g_deg[i] : 0;
    sm[t] = v;
    __syncthreads();
    for (int o = 1; o < SCAN_B; o <<= 1) {
        int u = (t >= o) ? sm[t - o] : 0;
        __syncthreads();
        sm[t] += u;
        __syncthreads();
    }
    if (i < n) {
        int excl = sm[t] - v + g_blockoff[blockIdx.x];
        g_off[i] = excl;
        g_cur[i] = excl;
        g_invdeg[i] = 1.0f / fmaxf((float)v, 1.0f);
    }
}

__global__ void fill_kernel(const int* __restrict__ src,
                            const int* __restrict__ dst, int E) {
    int e = blockIdx.x * blockDim.x + threadIdx.x;
    if (e < E) {
        int d = dst[e];
        int p = atomicAdd(&g_cur[d], 1);
        g_srcidx[p] = src[e];
    }
}

// ---------------------------------------------------------------------------
// Fused SAGE layer: CSR mean-gather + out = relu(mean@Wl^T + bl + in@Wr^T)
// Warp owns 8 nodes as 4 interleaved PAIRS; lane computes cols j=lane, lane+32.
// smem: sW = [Wl;Wr]^T as [k=0..127][j=0..63] pitch 65 (conflict-free);
//       sVI = per-pair interleaved features: sVI[pair][k] = (V_{2p}[k], V_{2p+1}[k])
// GEMM inner loop uses fma.rn.f32x2: one FFMA2 computes both nodes of a pair.
// insel: 0 -> read xin, 1 -> read g_h1.  outsel: 0 -> g_h1, 1 -> g_h2.
// ---------------------------------------------------------------------------
#define LAYER_SMEM_FLOATS (128 * 65 + 8 * 4 * 128 * 2)   // sW + 8 warps * 4 pairs * 128k * float2
#define LAYER_SMEM_BYTES  (LAYER_SMEM_FLOATS * 4)

__global__ __launch_bounds__(256) void layer_kernel(
    const float* __restrict__ xin, const float* __restrict__ Wl,
    const float* __restrict__ bl, const float* __restrict__ Wr,
    int insel, int outsel, int n)
{
    extern __shared__ float sm[];
    float* sW = sm;                    // 128 x 65
    float* sVI = sm + 128 * 65;        // 8 warps x 4 pairs x 128 x float2

    const float* in = insel ? g_h1 : xin;
    float* out = outsel ? g_h2 : g_h1;

    int tid = threadIdx.x;
    int lane = tid & 31;
    int w = tid >> 5;

    // Stage concatenated transposed weights: sW[k*65 + j]
    for (int idx = tid; idx < 2 * 64 * 64; idx += 256) {
        int m = idx >> 12;        // 0 -> Wl (mean), 1 -> Wr (self)
        int r = idx & 4095;       // j*64 + k (coalesced global read)
        int j = r >> 6;
        int k = r & 63;
        float wv = (m == 0) ? Wl[r] : Wr[r];
        sW[(m * 64 + k) * 65 + j] = wv;
    }
    __syncthreads();

    int base = blockIdx.x * 64 + w * 8;
    float* myV = sVI + w * (4 * 128 * 2);   // this warp's 4 pairs
    const float2* fb = (const float2*)in;

    // Gather 8 nodes; lane covers dims (2*lane, 2*lane+1) via float2 loads.
    for (int g = 0; g < 8; g++) {
        int node = base + g;
        int p = g >> 1, par = g & 1;
        float* vp = myV + p * 256 + par;   // interleaved: entry k at vp[2k]
        if (node < n) {
            int beg = g_off[node];
            int cnt = g_deg[node];
            float2 a0 = make_float2(0.f, 0.f), a1 = make_float2(0.f, 0.f);
            float2 a2 = make_float2(0.f, 0.f), a3 = make_float2(0.f, 0.f);
            int k = 0;
            for (; k + 4 <= cnt; k += 4) {
                int s0 = g_srcidx[beg + k];
                int s1 = g_srcidx[beg + k + 1];
                int s2 = g_srcidx[beg + k + 2];
                int s3 = g_srcidx[beg + k + 3];
                float2 v0 = fb[(long long)s0 * 32 + lane];
                float2 v1 = fb[(long long)s1 * 32 + lane];
                float2 v2 = fb[(long long)s2 * 32 + lane];
                float2 v3 = fb[(long long)s3 * 32 + lane];
                a0.x += v0.x; a0.y += v0.y;
                a1.x += v1.x; a1.y += v1.y;
                a2.x += v2.x; a2.y += v2.y;
                a3.x += v3.x; a3.y += v3.y;
            }
            for (; k < cnt; k++) {
                int s0 = g_srcidx[beg + k];
                float2 v0 = fb[(long long)s0 * 32 + lane];
                a0.x += v0.x; a0.y += v0.y;
            }
            float inv = g_invdeg[node];
            float mx = (a0.x + a1.x + a2.x + a3.x) * inv;
            float my = (a0.y + a1.y + a2.y + a3.y) * inv;
            float2 xv = fb[(long long)node * 32 + lane];
            vp[(2 * lane) * 2]          = mx;      // k = 2*lane       (mean)
            vp[(2 * lane + 1) * 2]      = my;      // k = 2*lane+1     (mean)
            vp[(64 + 2 * lane) * 2]     = xv.x;    // k = 64+2*lane    (self)
            vp[(64 + 2 * lane + 1) * 2] = xv.y;    // k = 64+2*lane+1  (self)
        } else {
            vp[(2 * lane) * 2] = 0.f;
            vp[(2 * lane + 1) * 2] = 0.f;
            vp[(64 + 2 * lane) * 2] = 0.f;
            vp[(64 + 2 * lane + 1) * 2] = 0.f;
        }
    }
    __syncwarp();

    // GEMM: acc[p][jh] is f32x2 pair (node 2p, node 2p+1) at column jh*32+lane
    unsigned long long acc[4][2];
#pragma unroll
    for (int p = 0; p < 4; p++) { acc[p][0] = 0ull; acc[p][1] = 0ull; }

    const unsigned long long* vbase = (const unsigned long long*)myV;
#pragma unroll 4
    for (int kk = 0; kk < 32; kk++) {
        unsigned long long ws0[4], ws1[4];
#pragma unroll
        for (int u = 0; u < 4; u++) {
            ws0[u] = splat2(sW[(kk * 4 + u) * 65 + lane]);
            ws1[u] = splat2(sW[(kk * 4 + u) * 65 + 32 + lane]);
        }
#pragma unroll
        for (int p = 0; p < 4; p++) {
            const unsigned long long* ap = vbase + p * 128 + kk * 4;
            ulonglong2 a01 = *(const ulonglong2*)(ap);       // k4+0, k4+1 (broadcast)
            ulonglong2 a23 = *(const ulonglong2*)(ap + 2);   // k4+2, k4+3
            acc[p][0] = fma2(a01.x, ws0[0], acc[p][0]);
            acc[p][1] = fma2(a01.x, ws1[0], acc[p][1]);
            acc[p][0] = fma2(a01.y, ws0[1], acc[p][0]);
            acc[p][1] = fma2(a01.y, ws1[1], acc[p][1]);
            acc[p][0] = fma2(a23.x, ws0[2], acc[p][0]);
            acc[p][1] = fma2(a23.x, ws1[2], acc[p][1]);
            acc[p][0] = fma2(a23.y, ws0[3], acc[p][0]);
            acc[p][1] = fma2(a23.y, ws1[3], acc[p][1]);
        }
    }

    float b0 = bl[lane];
    float b1 = bl[32 + lane];
#pragma unroll
    for (int p = 0; p < 4; p++) {
        int n0 = base + 2 * p, n1 = base + 2 * p + 1;
        float lo, hi;
        unpack2(acc[p][0], lo, hi);
        if (n0 < n) out[(long long)n0 * 64 + lane] = fmaxf(lo + b0, 0.f);
        if (n1 < n) out[(long long)n1 * 64 + lane] = fmaxf(hi + b0, 0.f);
        unpack2(acc[p][1], lo, hi);
        if (n0 < n) out[(long long)n0 * 64 + 32 + lane] = fmaxf(lo + b1, 0.f);
        if (n1 < n) out[(long long)n1 * 64 + 32 + lane] = fmaxf(hi + b1, 0.f);
    }
}

// ---------------------------------------------------------------------------
// Output head: logits = h2 @ Wout^T + bout; out = log_softmax(logits)
// ---------------------------------------------------------------------------
__global__ __launch_bounds__(256) void out_kernel(
    const float* __restrict__ Wout, const float* __restrict__ bout,
    float* __restrict__ out, int n)
{
    __shared__ __align__(16) float sW[64 * 65];
    __shared__ __align__(16) float sV[64 * 64];

    int tid = threadIdx.x;
    int lane = tid & 31;
    int w = tid >> 5;

    for (int idx = tid; idx < 64 * 64; idx += 256) {
        int j = idx >> 6;
        int k = idx & 63;
        sW[k * 65 + j] = Wout[idx];
    }

    int base = blockIdx.x * 64 + w * 8;

    for (int p = 0; p < 4; p++) {
        int g = p * 2 + (lane >> 4);
        int node = base + g;
        int q = lane & 15;
        float4 v = make_float4(0.f, 0.f, 0.f, 0.f);
        if (node < n) v = ((const float4*)g_h2)[(long long)node * 16 + q];
        ((float4*)(sV + (w * 8 + g) * 64))[q] = v;
    }
    __syncthreads();

    float acc[8][2];
#pragma unroll
    for (int g = 0; g < 8; g++) { acc[g][0] = 0.f; acc[g][1] = 0.f; }

    const float* vb = sV + (w * 8) * 64;
#pragma unroll 4
    for (int kk = 0; kk < 16; kk++) {
        float w0[4], w1[4];
#pragma unroll
        for (int u = 0; u < 4; u++) {
            w0[u] = sW[(kk * 4 + u) * 65 + lane];
            w1[u] = sW[(kk * 4 + u) * 65 + 32 + lane];
        }
#pragma unroll
        for (int g = 0; g < 8; g++) {
            float4 v = *(const float4*)(vb + g * 64 + kk * 4);
            acc[g][0] += v.x * w0[0] + v.y * w0[1] + v.z * w0[2] + v.w * w0[3];
            acc[g][1] += v.x * w1[0] + v.y * w1[1] + v.z * w1[2] + v.w * w1[3];
        }
    }

    float b0 = bout[lane];
    float b1 = bout[32 + lane];
#pragma unroll
    for (int g = 0; g < 8; g++) {
        int node = base + g;
        float l0 = acc[g][0] + b0;
        float l1 = acc[g][1] + b1;
        float m = fmaxf(l0, l1);
#pragma unroll
        for (int o = 16; o; o >>= 1) m = fmaxf(m, __shfl_xor_sync(0xffffffffu, m, o));
        float s = expf(l0 - m) + expf(l1 - m);
#pragma unroll
        for (int o = 16; o; o >>= 1) s += __shfl_xor_sync(0xffffffffu, s, o);
        float lse = m + logf(s);
        if (node < n) {
            out[(long long)node * 64 + lane]      = l0 - lse;
            out[(long long)node * 64 + 32 + lane] = l1 - lse;
        }
    }
}

// ---------------------------------------------------------------------------
// Launch
// ---------------------------------------------------------------------------
extern "C" void kernel_launch(void* const* d_in, const int* in_sizes, int n_in,
                              void* d_out, int out_size) {
    const float* x        = (const float*)d_in[0];
    const int*   ei       = (const int*)d_in[1];   // int32 (JAX x64 disabled)
    const float* W1l      = (const float*)d_in[2];
    const float* b1l      = (const float*)d_in[3];
    const float* W1r      = (const float*)d_in[4];
    const float* W2l      = (const float*)d_in[5];
    const float* b2l      = (const float*)d_in[6];
    const float* W2r      = (const float*)d_in[7];
    const float* Wout     = (const float*)d_in[8];
    const float* bout     = (const float*)d_in[9];
    float* out            = (float*)d_out;

    int n = in_sizes[0] / D;
    int E = in_sizes[1] / 2;
    const int* src = ei;        // row 0
    const int* dst = ei + E;    // row 1

    cudaFuncSetAttribute(layer_kernel,
                         cudaFuncAttributeMaxDynamicSharedMemorySize,
                         LAYER_SMEM_BYTES);

    int egrid = (E + 255) / 256;
    int ngrid = (n + 255) / 256;
    int lgrid = (n + 63) / 64;
    int sgrid = (n + SCAN_B - 1) / SCAN_B;   // 98 blocks

    // CSR build (shared by both layers) — parallel coalesced scan
    zero_deg_kernel<<<ngrid, 256>>>(n);
    deg_kernel<<<egrid, 256>>>(dst, E);
    scanA_kernel<<<sgrid, SCAN_B>>>(n);
    scanB_kernel<<<1, NBLK>>>(sgrid);
    scanC_kernel<<<sgrid, SCAN_B>>>(n);
    fill_kernel<<<egrid, 256>>>(src, dst, E);

    // Fused layers
    layer_kernel<<<lgrid, 256, LAYER_SMEM_BYTES>>>(x, W1l, b1l, W1r, 0, 0, n);
    layer_kernel<<<lgrid, 256, LAYER_SMEM_BYTES>>>(x, W2l, b2l, W2r, 1, 1, n);

    // Output head + log-softmax
    out_kernel<<<lgrid, 256>>>(Wout, bout, out, n);
}

// round 17
// speedup vs baseline: 1.0498x; 1.0498x over previous
#include <cuda_runtime.h>
#include <math.h>

// Fixed shape: N=100000, E=1600000, all dims 64.
#define MAXN 100000
#define MAXE 1600000
#define D 64
#define SCAN_B 1024
#define NBLK 128   // >= ceil(MAXN/SCAN_B) = 98

// Scratch (device globals; no allocation allowed)
__device__ float g_h1 [MAXN * D];
__device__ float g_h2 [MAXN * D];
__device__ int   g_deg[MAXN];
__device__ int   g_off[MAXN];
__device__ int   g_cur[MAXN];
__device__ int   g_srcidx[MAXE];
__device__ float g_invdeg[MAXN];
__device__ int   g_blocksum[NBLK];
__device__ int   g_blockoff[NBLK];

// ---------------------------------------------------------------------------
// CSR build
// ---------------------------------------------------------------------------
__global__ void zero_deg_kernel(int n) {
    int i = blockIdx.x * blockDim.x + threadIdx.x;
    if (i < n) g_deg[i] = 0;
}

__global__ void deg_kernel(const int* __restrict__ dst, int E) {
    int e = blockIdx.x * blockDim.x + threadIdx.x;
    if (e < E) atomicAdd(&g_deg[dst[e]], 1);
}

// Phase A: coalesced per-block reduction of deg
__global__ __launch_bounds__(SCAN_B) void scanA_kernel(int n) {
    int i = blockIdx.x * SCAN_B + threadIdx.x;
    int v = (i < n) ? g_deg[i] : 0;
#pragma unroll
    for (int o = 16; o; o >>= 1) v += __shfl_xor_sync(0xffffffffu, v, o);
    __shared__ int ws[32];
    if ((threadIdx.x & 31) == 0) ws[threadIdx.x >> 5] = v;
    __syncthreads();
    if (threadIdx.x < 32) {
        int s = ws[threadIdx.x];
#pragma unroll
        for (int o = 16; o; o >>= 1) s += __shfl_xor_sync(0xffffffffu, s, o);
        if (threadIdx.x == 0) g_blocksum[blockIdx.x] = s;
    }
}

// Phase B: single-block exclusive scan of block sums
__global__ __launch_bounds__(NBLK) void scanB_kernel(int nb) {
    __shared__ int s[NBLK];
    int t = threadIdx.x;
    int v = (t < nb) ? g_blocksum[t] : 0;
    s[t] = v;
    __syncthreads();
    for (int o = 1; o < NBLK; o <<= 1) {
        int u = (t >= o) ? s[t - o] : 0;
        __syncthreads();
        s[t] += u;
        __syncthreads();
    }
    g_blockoff[t] = s[t] - v;   // exclusive
}

// Phase C: per-block exclusive scan + offset; emits off/cur/invdeg (coalesced)
__global__ __launch_bounds__(SCAN_B) void scanC_kernel(int n) {
    __shared__ int sm[SCAN_B];
    int i = blockIdx.x * SCAN_B + threadIdx.x;
    int t = threadIdx.x;
    int v = (i < n) ? g_deg[i] : 0;
    sm[t] = v;
    __syncthreads();
    for (int o = 1; o < SCAN_B; o <<= 1) {
        int u = (t >= o) ? sm[t - o] : 0;
        __syncthreads();
        sm[t] += u;
        __syncthreads();
    }
    if (i < n) {
        int excl = sm[t] - v + g_blockoff[blockIdx.x];
        g_off[i] = excl;
        g_cur[i] = excl;
        g_invdeg[i] = 1.0f / fmaxf((float)v, 1.0f);
    }
}

// 4 edges per thread: independent atomic chains (MLP=4) instead of 1.
__global__ void fill_kernel(const int* __restrict__ src,
                            const int* __restrict__ dst, int E) {
    int e = (blockIdx.x * blockDim.x + threadIdx.x) * 4;
#pragma unroll
    for (int u = 0; u < 4; u++) {
        int ee = e + u;
        if (ee < E) {
            int d = dst[ee];
            int p = atomicAdd(&g_cur[d], 1);
            g_srcidx[p] = src[ee];
        }
    }
}

// ---------------------------------------------------------------------------
// Fused SAGE layer: CSR mean-gather + out = relu(mean@Wl^T + bl + in@Wr^T)
// Gather: half-warp scheme. Even half (lanes 0-15) takes even neighbor-list
// positions, odd half odd positions; 16 lanes cover a full 64-float row with
// one LDG.128 each, unrolled x4 (8 neighbors in flight/warp). Halves merged
// with 4 shfl_xor(16).  GEMM: proven R15 scalar-FFMA form.
// insel: 0 -> read xin, 1 -> read g_h1.  outsel: 0 -> g_h1, 1 -> g_h2.
// ---------------------------------------------------------------------------
#define LAYER_SMEM_FLOATS (128 * 65 + 64 * 128)
#define LAYER_SMEM_BYTES  (LAYER_SMEM_FLOATS * 4)

__global__ __launch_bounds__(256) void layer_kernel(
    const float* __restrict__ xin, const float* __restrict__ Wl,
    const float* __restrict__ bl, const float* __restrict__ Wr,
    int insel, int outsel, int n)
{
    extern __shared__ float sm[];
    float* sW = sm;              // 128 x 65
    float* sV = sm + 128 * 65;   // 64 nodes x 128

    const float* in = insel ? g_h1 : xin;
    float* out = outsel ? g_h2 : g_h1;

    int tid = threadIdx.x;
    int lane = tid & 31;
    int w = tid >> 5;

    // Stage concatenated transposed weights: sW[k*65 + j]
    for (int idx = tid; idx < 2 * 64 * 64; idx += 256) {
        int m = idx >> 12;        // 0 -> Wl (mean), 1 -> Wr (self)
        int r = idx & 4095;       // j*64 + k (coalesced global read)
        int j = r >> 6;
        int k = r & 63;
        float wv = (m == 0) ? Wl[r] : Wr[r];
        sW[(m * 64 + k) * 65 + j] = wv;
    }
    __syncthreads();

    int base = blockIdx.x * 64 + w * 8;
    const float4* fb4 = (const float4*)in;
    int h = lane >> 4;      // half-warp id: 0 = even positions, 1 = odd
    int q = lane & 15;      // float4 slot within row

    // Gather 8 nodes (deg is warp-uniform per node -> convergent loops)
    for (int g = 0; g < 8; g++) {
        int node = base + g;
        float* row = sV + (w * 8 + g) * 128;
        if (node < n) {
            int beg = g_off[node];
            int cnt = g_deg[node];
            float4 A0 = make_float4(0.f, 0.f, 0.f, 0.f);
            float4 A1 = make_float4(0.f, 0.f, 0.f, 0.f);
            float4 A2 = make_float4(0.f, 0.f, 0.f, 0.f);
            float4 A3 = make_float4(0.f, 0.f, 0.f, 0.f);
            int kb = 0;
            for (; kb + 8 <= cnt; kb += 8) {
                int k0 = beg + kb + h;
                int s0 = g_srcidx[k0];
                int s1 = g_srcidx[k0 + 2];
                int s2 = g_srcidx[k0 + 4];
                int s3 = g_srcidx[k0 + 6];
                float4 v0 = fb4[(long long)s0 * 16 + q];
                float4 v1 = fb4[(long long)s1 * 16 + q];
                float4 v2 = fb4[(long long)s2 * 16 + q];
                float4 v3 = fb4[(long long)s3 * 16 + q];
                A0.x += v0.x; A0.y += v0.y; A0.z += v0.z; A0.w += v0.w;
                A1.x += v1.x; A1.y += v1.y; A1.z += v1.z; A1.w += v1.w;
                A2.x += v2.x; A2.y += v2.y; A2.z += v2.z; A2.w += v2.w;
                A3.x += v3.x; A3.y += v3.y; A3.z += v3.z; A3.w += v3.w;
            }
            for (int k = kb + h; k < cnt; k += 2) {
                int s = g_srcidx[beg + k];
                float4 v = fb4[(long long)s * 16 + q];
                A0.x += v.x; A0.y += v.y; A0.z += v.z; A0.w += v.w;
            }
            float4 a;
            a.x = A0.x + A1.x + A2.x + A3.x;
            a.y = A0.y + A1.y + A2.y + A3.y;
            a.z = A0.z + A1.z + A2.z + A3.z;
            a.w = A0.w + A1.w + A2.w + A3.w;
            // merge even/odd halves
            a.x += __shfl_xor_sync(0xffffffffu, a.x, 16);
            a.y += __shfl_xor_sync(0xffffffffu, a.y, 16);
            a.z += __shfl_xor_sync(0xffffffffu, a.z, 16);
            a.w += __shfl_xor_sync(0xffffffffu, a.w, 16);
            float inv = g_invdeg[node];
            if (h == 0) {
                ((float4*)row)[q] = make_float4(a.x * inv, a.y * inv,
                                                a.z * inv, a.w * inv);
            } else {
                ((float4*)row)[16 + q] = fb4[(long long)node * 16 + q];
            }
        } else {
            ((float4*)row)[h * 16 + q] = make_float4(0.f, 0.f, 0.f, 0.f);
        }
    }
    __syncwarp();

    float acc[8][2];
#pragma unroll
    for (int g = 0; g < 8; g++) { acc[g][0] = 0.f; acc[g][1] = 0.f; }

    const float* vb = sV + (w * 8) * 128;
#pragma unroll 4
    for (int kk = 0; kk < 32; kk++) {
        float w0[4], w1[4];
#pragma unroll
        for (int u = 0; u < 4; u++) {
            w0[u] = sW[(kk * 4 + u) * 65 + lane];
            w1[u] = sW[(kk * 4 + u) * 65 + 32 + lane];
        }
#pragma unroll
        for (int g = 0; g < 8; g++) {
            float4 v = *(const float4*)(vb + g * 128 + kk * 4);  // broadcast
            acc[g][0] += v.x * w0[0] + v.y * w0[1] + v.z * w0[2] + v.w * w0[3];
            acc[g][1] += v.x * w1[0] + v.y * w1[1] + v.z * w1[2] + v.w * w1[3];
        }
    }

    float b0 = bl[lane];
    float b1 = bl[32 + lane];
#pragma unroll
    for (int g = 0; g < 8; g++) {
        int node = base + g;
        if (node < n) {
            out[(long long)node * 64 + lane]      = fmaxf(acc[g][0] + b0, 0.f);
            out[(long long)node * 64 + 32 + lane] = fmaxf(acc[g][1] + b1, 0.f);
        }
    }
}

// ---------------------------------------------------------------------------
// Output head: logits = h2 @ Wout^T + bout; out = log_softmax(logits)
// ---------------------------------------------------------------------------
__global__ __launch_bounds__(256) void out_kernel(
    const float* __restrict__ Wout, const float* __restrict__ bout,
    float* __restrict__ out, int n)
{
    __shared__ __align__(16) float sW[64 * 65];
    __shared__ __align__(16) float sV[64 * 64];

    int tid = threadIdx.x;
    int lane = tid & 31;
    int w = tid >> 5;

    for (int idx = tid; idx < 64 * 64; idx += 256) {
        int j = idx >> 6;
        int k = idx & 63;
        sW[k * 65 + j] = Wout[idx];
    }

    int base = blockIdx.x * 64 + w * 8;

    for (int p = 0; p < 4; p++) {
        int g = p * 2 + (lane >> 4);
        int node = base + g;
        int q = lane & 15;
        float4 v = make_float4(0.f, 0.f, 0.f, 0.f);
        if (node < n) v = ((const float4*)g_h2)[(long long)node * 16 + q];
        ((float4*)(sV + (w * 8 + g) * 64))[q] = v;
    }
    __syncthreads();

    float acc[8][2];
#pragma unroll
    for (int g = 0; g < 8; g++) { acc[g][0] = 0.f; acc[g][1] = 0.f; }

    const float* vb = sV + (w * 8) * 64;
#pragma unroll 4
    for (int kk = 0; kk < 16; kk++) {
        float w0[4], w1[4];
#pragma unroll
        for (int u = 0; u < 4; u++) {
            w0[u] = sW[(kk * 4 + u) * 65 + lane];
            w1[u] = sW[(kk * 4 + u) * 65 + 32 + lane];
        }
#pragma unroll
        for (int g = 0; g < 8; g++) {
            float4 v = *(const float4*)(vb + g * 64 + kk * 4);
            acc[g][0] += v.x * w0[0] + v.y * w0[1] + v.z * w0[2] + v.w * w0[3];
            acc[g][1] += v.x * w1[0] + v.y * w1[1] + v.z * w1[2] + v.w * w1[3];
        }
    }

    float b0 = bout[lane];
    float b1 = bout[32 + lane];
#pragma unroll
    for (int g = 0; g < 8; g++) {
        int node = base + g;
        float l0 = acc[g][0] + b0;
        float l1 = acc[g][1] + b1;
        float m = fmaxf(l0, l1);
#pragma unroll
        for (int o = 16; o; o >>= 1) m = fmaxf(m, __shfl_xor_sync(0xffffffffu, m, o));
        float s = expf(l0 - m) + expf(l1 - m);
#pragma unroll
        for (int o = 16; o; o >>= 1) s += __shfl_xor_sync(0xffffffffu, s, o);
        float lse = m + logf(s);
        if (node < n) {
            out[(long long)node * 64 + lane]      = l0 - lse;
            out[(long long)node * 64 + 32 + lane] = l1 - lse;
        }
    }
}

// ---------------------------------------------------------------------------
// Launch
// ---------------------------------------------------------------------------
extern "C" void kernel_launch(void* const* d_in, const int* in_sizes, int n_in,
                              void* d_out, int out_size) {
    const float* x        = (const float*)d_in[0];
    const int*   ei       = (const int*)d_in[1];   // int32 (JAX x64 disabled)
    const float* W1l      = (const float*)d_in[2];
    const float* b1l      = (const float*)d_in[3];
    const float* W1r      = (const float*)d_in[4];
    const float* W2l      = (const float*)d_in[5];
    const float* b2l      = (const float*)d_in[6];
    const float* W2r      = (const float*)d_in[7];
    const float* Wout     = (const float*)d_in[8];
    const float* bout     = (const float*)d_in[9];
    float* out            = (float*)d_out;

    int n = in_sizes[0] / D;
    int E = in_sizes[1] / 2;
    const int* src = ei;        // row 0
    const int* dst = ei + E;    // row 1

    cudaFuncSetAttribute(layer_kernel,
                         cudaFuncAttributeMaxDynamicSharedMemorySize,
                         LAYER_SMEM_BYTES);

    int egrid = (E + 255) / 256;
    int fgrid = (E + 1023) / 1024;           // fill: 4 edges/thread
    int ngrid = (n + 255) / 256;
    int lgrid = (n + 63) / 64;
    int sgrid = (n + SCAN_B - 1) / SCAN_B;   // 98 blocks

    // CSR build (shared by both layers) — parallel coalesced scan
    zero_deg_kernel<<<ngrid, 256>>>(n);
    deg_kernel<<<egrid, 256>>>(dst, E);
    scanA_kernel<<<sgrid, SCAN_B>>>(n);
    scanB_kernel<<<1, NBLK>>>(sgrid);
    scanC_kernel<<<sgrid, SCAN_B>>>(n);
    fill_kernel<<<fgrid, 256>>>(src, dst, E);

    // Fused layers
    layer_kernel<<<lgrid, 256, LAYER_SMEM_BYTES>>>(x, W1l, b1l, W1r, 0, 0, n);
    layer_kernel<<<lgrid, 256, LAYER_SMEM_BYTES>>>(x, W2l, b2l, W2r, 1, 1, n);

    // Output head + log-softmax
    out_kernel<<<lgrid, 256>>>(Wout, bout, out, n);
}